// round 13
// baseline (speedup 1.0000x reference)
#include <cuda_runtime.h>
#include <cuda_fp16.h>
#include <cstdint>
#include <math.h>

#define NTOK 4096
#define EMB 1024
#define FFD 4096
#define SEQ 2048

// ---------------- scratch (device globals: no runtime allocation) ----------
__device__ __half g_ln1[NTOK * EMB];
__device__ __half g_q[NTOK * EMB];
__device__ __half g_k[NTOK * EMB];
__device__ __half g_v[NTOK * EMB];
__device__ __half g_attn[NTOK * EMB];
__device__ float  g_x1[NTOK * EMB];
__device__ __half g_ln2[NTOK * EMB];
__device__ __half g_ff[NTOK * FFD];
__device__ __half g_WqkvT[3 * EMB * EMB];
__device__ float  g_bqkv[3 * EMB];
__device__ __half g_WoT[EMB * EMB];
__device__ __half g_W1T[EMB * FFD];
__device__ __half g_W2T[FFD * EMB];

// ---------------- small helpers --------------------------------------------
__device__ __forceinline__ uint32_t smem_u32(const void* p) {
    uint32_t a;
    asm("{ .reg .u64 t; cvta.to.shared.u64 t, %1; cvt.u32.u64 %0, t; }"
        : "=r"(a) : "l"(p));
    return a;
}
__device__ __forceinline__ void cp16(uint32_t dst, const void* src) {
    asm volatile("cp.async.cg.shared.global [%0], [%1], 16;"
                 :: "r"(dst), "l"(src) : "memory");
}

// m16n8k16 fp16 mma, f32 accumulate (family-portable, sm_80+)
#define MMA_F16(d, a, b)                                                      \
    asm volatile("mma.sync.aligned.m16n8k16.row.col.f32.f16.f16.f32 "         \
        "{%0,%1,%2,%3}, {%4,%5,%6,%7}, {%8,%9}, {%0,%1,%2,%3};"               \
        : "+f"((d)[0]), "+f"((d)[1]), "+f"((d)[2]), "+f"((d)[3])              \
        : "r"((a)[0]), "r"((a)[1]), "r"((a)[2]), "r"((a)[3]),                 \
          "r"((b)[0]), "r"((b)[1]))

// transposed 8x8 b16 ldmatrix x4 (trans variant only — non-trans kills the toolchain)
#define LDSM4T(r0, r1, r2, r3, addr)                                          \
    asm volatile("ldmatrix.sync.aligned.m8n8.x4.trans.shared.b16 "            \
        "{%0,%1,%2,%3}, [%4];"                                                \
        : "=r"(r0), "=r"(r1), "=r"(r2), "=r"(r3) : "r"(addr))

#define PITCH 72                        // halves per smem row
#define PITCH2 (PITCH * 2)              // bytes per row
#define TILE_H (128 * PITCH)            // halves per 128-row tile
#define BUF_H  (2 * TILE_H)             // A + B per stage (halves)
#define GSMEM_BYTES (3 * BUF_H * 2)     // 110592 B, 3-stage

// ---------------- fp16 tensor-core GEMM: C = A[M,K] @ Bt[N,K]^T + bias -----
// MODE 1: GELU -> half Ch   MODE 2: + residual R -> float Cf
// MODE 3: qkv split (q-segment additionally scaled by 0.125 for attention)
template <int MODE>
__global__ __launch_bounds__(256) void gemm_mma(
    const __half* __restrict__ A, const __half* __restrict__ Bt,
    const float* __restrict__ bias, const float* __restrict__ R,
    float* __restrict__ Cf, __half* __restrict__ Ch,
    __half* __restrict__ Ch2, __half* __restrict__ Ch3,
    int M, int N, int K)
{
    extern __shared__ __half smh[];
    uint32_t sb = smem_u32(smh);

    int tid = threadIdx.x, wid = tid >> 5, lane = tid & 31;
    int tr = lane >> 2, tc = lane & 3;
    int wm0 = (wid >> 1) * 32, wn0 = (wid & 1) * 64;
    int m0 = blockIdx.y * 128, n0 = blockIdx.x * 128;

    float acc[2][8][4];
    #pragma unroll
    for (int i = 0; i < 2; i++)
        #pragma unroll
        for (int j = 0; j < 8; j++)
            #pragma unroll
            for (int r = 0; r < 4; r++) acc[i][j][r] = 0.f;

    const int NC = K >> 6;    // K-chunks of 64

    auto load_chunk = [&](int c) {
        uint32_t ab = sb + (uint32_t)(c % 3) * (BUF_H * 2);
        uint32_t bb = ab + TILE_H * 2;
        const __half* Ap = A + (size_t)m0 * K + (c << 6);
        const __half* Bp = Bt + (size_t)n0 * K + (c << 6);
        #pragma unroll
        for (int i = 0; i < 4; i++) {
            int gid = (i << 8) + tid;          // 0..1023
            int row = gid >> 3, g = gid & 7;   // 128 rows x 8 16B-groups
            uint32_t doff = (uint32_t)row * PITCH2 + (uint32_t)g * 16;
            cp16(ab + doff, Ap + (size_t)row * K + g * 8);
            cp16(bb + doff, Bp + (size_t)row * K + g * 8);
        }
        asm volatile("cp.async.commit_group;" ::: "memory");
    };

    load_chunk(0);
    load_chunk(1);
    for (int c = 0; c < NC; c++) {
        if (c + 1 < NC)
            asm volatile("cp.async.wait_group 1;" ::: "memory");
        else
            asm volatile("cp.async.wait_group 0;" ::: "memory");
        __syncthreads();        // single barrier per chunk (3-stage)
        if (c + 2 < NC) load_chunk(c + 2);

        const __half* Af = smh + (size_t)(c % 3) * BUF_H;
        const __half* Bf = Af + TILE_H;
        #pragma unroll
        for (int kk = 0; kk < 4; kk++) {      // 4 x k16
            int k0 = kk << 4;
            uint32_t a[2][4];
            #pragma unroll
            for (int mf = 0; mf < 2; mf++) {
                int r = wm0 + mf * 16 + tr;
                a[mf][0] = *(const uint32_t*)&Af[r * PITCH + k0 + 2 * tc];
                a[mf][1] = *(const uint32_t*)&Af[(r + 8) * PITCH + k0 + 2 * tc];
                a[mf][2] = *(const uint32_t*)&Af[r * PITCH + k0 + 8 + 2 * tc];
                a[mf][3] = *(const uint32_t*)&Af[(r + 8) * PITCH + k0 + 8 + 2 * tc];
            }
            uint32_t b[8][2];
            #pragma unroll
            for (int nf = 0; nf < 8; nf++) {
                int r = wn0 + nf * 8 + tr;
                b[nf][0] = *(const uint32_t*)&Bf[r * PITCH + k0 + 2 * tc];
                b[nf][1] = *(const uint32_t*)&Bf[r * PITCH + k0 + 8 + 2 * tc];
            }
            #pragma unroll
            for (int mf = 0; mf < 2; mf++)
                #pragma unroll
                for (int nf = 0; nf < 8; nf++)
                    MMA_F16(acc[mf][nf], a[mf], b[nf]);
        }
    }

    // epilogue
    #pragma unroll
    for (int mf = 0; mf < 2; mf++) {
        int rbase = m0 + wm0 + mf * 16 + tr;
        #pragma unroll
        for (int nf = 0; nf < 8; nf++) {
            int col = wn0 + nf * 8 + tc * 2;
            float b0 = bias[n0 + col], b1 = bias[n0 + col + 1];
            float v0 = acc[mf][nf][0] + b0;
            float v1 = acc[mf][nf][1] + b1;
            float v2 = acc[mf][nf][2] + b0;
            float v3 = acc[mf][nf][3] + b1;
            if (MODE == 1) {
                #define GELU(v) (0.5f * (v) * (1.0f + tanhf(0.7978845608028654f * ((v) + 0.044715f * (v) * (v) * (v)))))
                v0 = GELU(v0); v1 = GELU(v1); v2 = GELU(v2); v3 = GELU(v3);
                #undef GELU
                *(__half2*)(Ch + (size_t)rbase * N + n0 + col) = __floats2half2_rn(v0, v1);
                *(__half2*)(Ch + (size_t)(rbase + 8) * N + n0 + col) = __floats2half2_rn(v2, v3);
            } else if (MODE == 2) {
                float2 r0 = *(const float2*)(R + (size_t)rbase * N + n0 + col);
                float2 r1 = *(const float2*)(R + (size_t)(rbase + 8) * N + n0 + col);
                v0 += r0.x; v1 += r0.y; v2 += r1.x; v3 += r1.y;
                *(float2*)(Cf + (size_t)rbase * N + n0 + col) = make_float2(v0, v1);
                *(float2*)(Cf + (size_t)(rbase + 8) * N + n0 + col) = make_float2(v2, v3);
            } else {
                int seg = n0 >> 10;
                __half* Out = (seg == 0) ? Ch : (seg == 1) ? Ch2 : Ch3;
                if (seg == 0) {  // q: fold in 1/sqrt(64)
                    v0 *= 0.125f; v1 *= 0.125f; v2 *= 0.125f; v3 *= 0.125f;
                }
                int oc = (n0 & 1023) + col;
                *(__half2*)(Out + (size_t)rbase * EMB + oc) = __floats2half2_rn(v0, v1);
                *(__half2*)(Out + (size_t)(rbase + 8) * EMB + oc) = __floats2half2_rn(v2, v3);
            }
        }
    }
}

// ---------------- weight prep ----------------------------------------------
__global__ __launch_bounds__(256) void prep_qkv(
    const float* __restrict__ Wq, const float* __restrict__ Wk,
    const float* __restrict__ Wv,
    const float* __restrict__ bq, const float* __restrict__ bk,
    const float* __restrict__ bv,
    __half* __restrict__ WqkvT, float* __restrict__ bqkv)
{
    __shared__ float t[32][33];
    int z = blockIdx.z;
    const float* W = (z == 0) ? Wq : (z == 1) ? Wk : Wv;
    const float* bs = (z == 0) ? bq : (z == 1) ? bk : bv;
    __half* Wt = WqkvT + (size_t)z * EMB * EMB;
    int bx = blockIdx.x * 32, by = blockIdx.y * 32;
    int x = threadIdx.x, y = threadIdx.y;
    if (blockIdx.y == 0 && y == 0)
        bqkv[z * EMB + bx + x] = bs[bx + x];
    #pragma unroll
    for (int r = 0; r < 32; r += 8)
        t[y + r][x] = W[(size_t)(by + y + r) * EMB + bx + x];
    __syncthreads();
    #pragma unroll
    for (int r = 0; r < 32; r += 8)
        Wt[(size_t)(bx + y + r) * EMB + by + x] = __float2half_rn(t[x][y + r]);
}

// one launch transposing Wo (1024 tiles), W1 (4096), W2 (4096); 1-D flattened
__global__ __launch_bounds__(256) void prep_t3(
    const float* __restrict__ Wo, const float* __restrict__ W1,
    const float* __restrict__ W2,
    __half* __restrict__ WoT, __half* __restrict__ W1T, __half* __restrict__ W2T)
{
    __shared__ float t[32][33];
    int bid = blockIdx.x;
    const float* W; __half* Wt; int K, N, tix, tiy;
    if (bid < 1024) {                  // Wo: 32x32 tiles
        W = Wo; Wt = WoT; K = EMB; N = EMB;
        tix = bid & 31; tiy = bid >> 5;
    } else if (bid < 5120) {           // W1: K=EMB, N=FFD -> 128x32 tiles
        int b = bid - 1024;
        W = W1; Wt = W1T; K = EMB; N = FFD;
        tix = b & 127; tiy = b >> 7;
    } else {                           // W2: K=FFD, N=EMB -> 32x128 tiles
        int b = bid - 5120;
        W = W2; Wt = W2T; K = FFD; N = EMB;
        tix = b & 31; tiy = b >> 5;
    }
    int bx = tix * 32, by = tiy * 32;
    int x = threadIdx.x, y = threadIdx.y;
    #pragma unroll
    for (int r = 0; r < 32; r += 8)
        t[y + r][x] = W[(size_t)(by + y + r) * N + bx + x];
    __syncthreads();
    #pragma unroll
    for (int r = 0; r < 32; r += 8)
        Wt[(size_t)(bx + y + r) * K + by + x] = __float2half_rn(t[x][y + r]);
}

// ---------------- layernorm: fp32 in, fp16 out ------------------------------
__global__ __launch_bounds__(256) void ln_kernel(
    const float* __restrict__ x, const float* __restrict__ g,
    const float* __restrict__ b, __half* __restrict__ out)
{
    int row = blockIdx.x;
    const float4* xr = (const float4*)(x + (size_t)row * EMB);
    float4 v = xr[threadIdx.x];
    float s  = v.x + v.y + v.z + v.w;
    float ss = v.x * v.x + v.y * v.y + v.z * v.z + v.w * v.w;
    #pragma unroll
    for (int o = 16; o; o >>= 1) {
        s  += __shfl_xor_sync(0xFFFFFFFFu, s,  o);
        ss += __shfl_xor_sync(0xFFFFFFFFu, ss, o);
    }
    __shared__ float sbuf[8], ssbuf[8];
    int w = threadIdx.x >> 5, l = threadIdx.x & 31;
    if (l == 0) { sbuf[w] = s; ssbuf[w] = ss; }
    __syncthreads();
    if (w == 0) {
        float s2  = (l < 8) ? sbuf[l]  : 0.f;
        float ss2 = (l < 8) ? ssbuf[l] : 0.f;
        #pragma unroll
        for (int o = 4; o; o >>= 1) {
            s2  += __shfl_xor_sync(0xFFFFFFFFu, s2,  o);
            ss2 += __shfl_xor_sync(0xFFFFFFFFu, ss2, o);
        }
        if (l == 0) { sbuf[0] = s2 * (1.f / EMB); ssbuf[0] = ss2 * (1.f / EMB); }
    }
    __syncthreads();
    float mean = sbuf[0];
    float var  = ssbuf[0] - mean * mean;
    float r    = rsqrtf(var + 1e-5f);
    float4 gg = ((const float4*)g)[threadIdx.x];
    float4 bb = ((const float4*)b)[threadIdx.x];
    __half2 h01 = __floats2half2_rn((v.x - mean) * r * gg.x + bb.x,
                                    (v.y - mean) * r * gg.y + bb.y);
    __half2 h23 = __floats2half2_rn((v.z - mean) * r * gg.z + bb.z,
                                    (v.w - mean) * r * gg.w + bb.w);
    uint2 u;
    u.x = *(uint32_t*)&h01; u.y = *(uint32_t*)&h23;
    ((uint2*)(out + (size_t)row * EMB))[threadIdx.x] = u;
}

// ---------------- flash attention, fp16 MMA, register-resident P ------------
#define KB_H   (64 * PITCH)             // halves per K (or V) tile
#define STG_H  (2 * KB_H)               // K+V per stage (halves)
#define ATTN_SMEM ((2 * STG_H + 128 * PITCH) * 2)   // 55296 B
__global__ __launch_bounds__(256) void attn_mma(
    const __half* __restrict__ Q, const __half* __restrict__ K,
    const __half* __restrict__ V, __half* __restrict__ O)
{
    extern __shared__ __half smh[];
    __half* QP = smh + 2 * STG_H;
    uint32_t smb = smem_u32(smh);

    int qt = blockIdx.x, h = blockIdx.y, b = blockIdx.z;
    int tid = threadIdx.x, wid = tid >> 5, lane = tid & 31;
    int tr = lane >> 2, tc = lane & 3;

    size_t qrow0 = (size_t)b * SEQ + qt * 128;

    // stage Q tile (128x64 halves) — already scaled by 0.125 in QKV epilogue
    for (int i = tid; i < 128 * 8; i += 256) {
        int r = i >> 3, g = i & 7;
        uint4 u = *(const uint4*)(Q + (qrow0 + r) * EMB + h * 64 + g * 8);
        *(uint4*)&QP[r * PITCH + g * 8] = u;
    }
    __syncthreads();

    int qr = wid * 16;
    uint32_t qf[4][4];
    #pragma unroll
    for (int kk = 0; kk < 4; kk++) {
        int k0 = kk << 4;
        qf[kk][0] = *(const uint32_t*)&QP[(qr + tr) * PITCH + k0 + 2 * tc];
        qf[kk][1] = *(const uint32_t*)&QP[(qr + tr + 8) * PITCH + k0 + 2 * tc];
        qf[kk][2] = *(const uint32_t*)&QP[(qr + tr) * PITCH + k0 + 8 + 2 * tc];
        qf[kk][3] = *(const uint32_t*)&QP[(qr + tr + 8) * PITCH + k0 + 8 + 2 * tc];
    }

    // V ldmatrix.trans invariant offsets
    int lm_krow = (lane & 7) + ((lane >> 3) & 1) * 8;
    int lm_ncol = (lane >> 4) * 8;

    float oacc[8][4];
    #pragma unroll
    for (int nf = 0; nf < 8; nf++)
        #pragma unroll
        for (int r = 0; r < 4; r++) oacc[nf][r] = 0.f;
    float m0 = -1e30f, m1 = -1e30f, l0 = 0.f, l1 = 0.f;

    size_t krow0 = (size_t)b * SEQ;
    auto load_tile = [&](int kt) {
        uint32_t stg = smb + (uint32_t)(kt & 1) * (STG_H * 2);
        for (int i = tid; i < 1024; i += 256) {
            int tile = i >> 9, idx = i & 511;
            int r = idx >> 3, g = idx & 7;
            size_t src = (krow0 + kt * 64 + r) * EMB + h * 64 + g * 8;
            uint32_t doff = (uint32_t)tile * (KB_H * 2) + (uint32_t)r * PITCH2 + g * 16;
            cp16(stg + doff, ((tile == 0) ? K : V) + src);
        }
        asm volatile("cp.async.commit_group;" ::: "memory");
    };

    load_tile(0);
    for (int kt = 0; kt < SEQ / 64; kt++) {
        asm volatile("cp.async.wait_group 0;" ::: "memory");
        __syncthreads();
        if (kt + 1 < SEQ / 64) load_tile(kt + 1);

        const __half* Ks = smh + (size_t)(kt & 1) * STG_H;
        uint32_t vbase = smb + (uint32_t)(kt & 1) * (STG_H * 2) + KB_H * 2;

        // S = Qs @ K^T
        float sacc[8][4];
        #pragma unroll
        for (int nf = 0; nf < 8; nf++)
            #pragma unroll
            for (int r = 0; r < 4; r++) sacc[nf][r] = 0.f;
        #pragma unroll
        for (int kk = 0; kk < 4; kk++) {
            int k0 = kk << 4;
            #pragma unroll
            for (int nf = 0; nf < 8; nf++) {
                uint32_t bfr[2];
                bfr[0] = *(const uint32_t*)&Ks[(nf * 8 + tr) * PITCH + k0 + 2 * tc];
                bfr[1] = *(const uint32_t*)&Ks[(nf * 8 + tr) * PITCH + k0 + 8 + 2 * tc];
                MMA_F16(sacc[nf], qf[kk], bfr);
            }
        }

        // online softmax -> P in registers
        float mt0 = -1e30f, mt1 = -1e30f;
        #pragma unroll
        for (int nf = 0; nf < 8; nf++) {
            mt0 = fmaxf(mt0, fmaxf(sacc[nf][0], sacc[nf][1]));
            mt1 = fmaxf(mt1, fmaxf(sacc[nf][2], sacc[nf][3]));
        }
        mt0 = fmaxf(mt0, __shfl_xor_sync(0xFFFFFFFFu, mt0, 1));
        mt0 = fmaxf(mt0, __shfl_xor_sync(0xFFFFFFFFu, mt0, 2));
        mt1 = fmaxf(mt1, __shfl_xor_sync(0xFFFFFFFFu, mt1, 1));
        mt1 = fmaxf(mt1, __shfl_xor_sync(0xFFFFFFFFu, mt1, 2));
        float mn0 = fmaxf(m0, mt0), mn1 = fmaxf(m1, mt1);
        float a0 = __expf(m0 - mn0), a1 = __expf(m1 - mn1);
        float rs0 = 0.f, rs1 = 0.f;
        uint32_t ph01[8], ph23[8];
        #pragma unroll
        for (int nf = 0; nf < 8; nf++) {
            float p0 = __expf(sacc[nf][0] - mn0);
            float p1 = __expf(sacc[nf][1] - mn0);
            float p2 = __expf(sacc[nf][2] - mn1);
            float p3 = __expf(sacc[nf][3] - mn1);
            rs0 += p0 + p1; rs1 += p2 + p3;
            __half2 h01 = __floats2half2_rn(p0, p1);
            __half2 h23 = __floats2half2_rn(p2, p3);
            ph01[nf] = *(uint32_t*)&h01;
            ph23[nf] = *(uint32_t*)&h23;
        }
        rs0 += __shfl_xor_sync(0xFFFFFFFFu, rs0, 1);
        rs0 += __shfl_xor_sync(0xFFFFFFFFu, rs0, 2);
        rs1 += __shfl_xor_sync(0xFFFFFFFFu, rs1, 1);
        rs1 += __shfl_xor_sync(0xFFFFFFFFu, rs1, 2);
        l0 = l0 * a0 + rs0; l1 = l1 * a1 + rs1;
        m0 = mn0; m1 = mn1;
        #pragma unroll
        for (int nf = 0; nf < 8; nf++) {
            oacc[nf][0] *= a0; oacc[nf][1] *= a0;
            oacc[nf][2] *= a1; oacc[nf][3] *= a1;
        }

        // O += P @ V   (P register-direct; V via ldmatrix.trans)
        #pragma unroll
        for (int kk = 0; kk < 4; kk++) {
            uint32_t pa[4] = {ph01[2 * kk], ph23[2 * kk],
                              ph01[2 * kk + 1], ph23[2 * kk + 1]};
            #pragma unroll
            for (int nfp = 0; nfp < 4; nfp++) {
                uint32_t v0, v1, v2, v3;
                uint32_t maddr = vbase +
                    (uint32_t)(kk * 16 + lm_krow) * PITCH2 +
                    (uint32_t)(nfp * 16 + lm_ncol) * 2;
                LDSM4T(v0, v1, v2, v3, maddr);
                uint32_t bA[2] = {v0, v1}, bB[2] = {v2, v3};
                MMA_F16(oacc[2 * nfp],     pa, bA);
                MMA_F16(oacc[2 * nfp + 1], pa, bB);
            }
        }
    }

    float i0 = 1.f / l0, i1 = 1.f / l1;
    size_t r0 = (qrow0 + qr + tr) * EMB + h * 64;
    size_t r1 = (qrow0 + qr + tr + 8) * EMB + h * 64;
    #pragma unroll
    for (int nf = 0; nf < 8; nf++) {
        int col = nf * 8 + tc * 2;
        *(__half2*)(O + r0 + col) = __floats2half2_rn(oacc[nf][0] * i0, oacc[nf][1] * i0);
        *(__half2*)(O + r1 + col) = __floats2half2_rn(oacc[nf][2] * i1, oacc[nf][3] * i1);
    }
}

// ---------------- launch ----------------------------------------------------
extern "C" void kernel_launch(void* const* d_in, const int* in_sizes, int n_in,
                              void* d_out, int out_size)
{
    const float* x     = (const float*)d_in[0];
    const float* Wq    = (const float*)d_in[1];
    const float* bq    = (const float*)d_in[2];
    const float* Wk    = (const float*)d_in[3];
    const float* bk    = (const float*)d_in[4];
    const float* Wv    = (const float*)d_in[5];
    const float* bv    = (const float*)d_in[6];
    const float* Wo    = (const float*)d_in[7];
    const float* bo    = (const float*)d_in[8];
    const float* W1    = (const float*)d_in[9];
    const float* b1    = (const float*)d_in[10];
    const float* W2    = (const float*)d_in[11];
    const float* b2    = (const float*)d_in[12];
    const float* ln1_g = (const float*)d_in[13];
    const float* ln1_b = (const float*)d_in[14];
    const float* ln2_g = (const float*)d_in[15];
    const float* ln2_b = (const float*)d_in[16];

    __half *ln1, *q, *k, *v, *attn, *ln2, *ff;
    __half *WqkvT, *WoT, *W1T, *W2T;
    float *x1, *bqkv;
    cudaGetSymbolAddress((void**)&ln1,   g_ln1);
    cudaGetSymbolAddress((void**)&q,     g_q);
    cudaGetSymbolAddress((void**)&k,     g_k);
    cudaGetSymbolAddress((void**)&v,     g_v);
    cudaGetSymbolAddress((void**)&attn,  g_attn);
    cudaGetSymbolAddress((void**)&x1,    g_x1);
    cudaGetSymbolAddress((void**)&ln2,   g_ln2);
    cudaGetSymbolAddress((void**)&ff,    g_ff);
    cudaGetSymbolAddress((void**)&WqkvT, g_WqkvT);
    cudaGetSymbolAddress((void**)&bqkv,  g_bqkv);
    cudaGetSymbolAddress((void**)&WoT,   g_WoT);
    cudaGetSymbolAddress((void**)&W1T,   g_W1T);
    cudaGetSymbolAddress((void**)&W2T,   g_W2T);

    cudaFuncSetAttribute(gemm_mma<1>, cudaFuncAttributeMaxDynamicSharedMemorySize, GSMEM_BYTES);
    cudaFuncSetAttribute(gemm_mma<2>, cudaFuncAttributeMaxDynamicSharedMemorySize, GSMEM_BYTES);
    cudaFuncSetAttribute(gemm_mma<3>, cudaFuncAttributeMaxDynamicSharedMemorySize, GSMEM_BYTES);
    cudaFuncSetAttribute(attn_mma, cudaFuncAttributeMaxDynamicSharedMemorySize, ATTN_SMEM);

    dim3 tb(32, 8);
    // launch 0
    prep_qkv<<<dim3(32, 32, 3), tb>>>(Wq, Wk, Wv, bq, bk, bv, WqkvT, bqkv);
    // launch 1: all remaining transposes in one go
    prep_t3<<<9216, tb>>>(Wo, W1, W2, WoT, W1T, W2T);
    // launch 2
    ln_kernel<<<NTOK, 256>>>(x, ln1_g, ln1_b, ln1);
    // launch 3 (observed ncu capture slot): fused QKV GEMM
    gemm_mma<3><<<dim3(3 * EMB / 128, NTOK / 128), 256, GSMEM_BYTES>>>(
        ln1, WqkvT, bqkv, nullptr, nullptr, q, k, v, NTOK, 3 * EMB, EMB);
    // launch 4
    attn_mma<<<dim3(SEQ / 128, 16, 2), 256, ATTN_SMEM>>>(q, k, v, attn);
    // launch 5
    gemm_mma<2><<<dim3(EMB / 128, NTOK / 128), 256, GSMEM_BYTES>>>(
        attn, WoT, bo, x, x1, nullptr, nullptr, nullptr, NTOK, EMB, EMB);
    // launch 6
    ln_kernel<<<NTOK, 256>>>(x1, ln2_g, ln2_b, ln2);
    // launch 7
    gemm_mma<1><<<dim3(FFD / 128, NTOK / 128), 256, GSMEM_BYTES>>>(
        ln2, W1T, b1, nullptr, nullptr, ff, nullptr, nullptr, NTOK, FFD, EMB);
    // launch 8
    gemm_mma<2><<<dim3(EMB / 128, NTOK / 128), 256, GSMEM_BYTES>>>(
        ff, W2T, b2, x1, (float*)d_out, nullptr, nullptr, nullptr, NTOK, EMB, FFD);
}

// round 16
// speedup vs baseline: 1.0650x; 1.0650x over previous
#include <cuda_runtime.h>
#include <cuda_fp16.h>
#include <cstdint>
#include <math.h>

#define NTOK 4096
#define EMB 1024
#define FFD 4096
#define SEQ 2048

// ---------------- scratch (device globals: no runtime allocation) ----------
__device__ __half g_ln1[NTOK * EMB];
__device__ __half g_q[NTOK * EMB];
__device__ __half g_k[NTOK * EMB];
__device__ __half g_v[NTOK * EMB];
__device__ __half g_attn[NTOK * EMB];
__device__ float  g_x1[NTOK * EMB];
__device__ __half g_ln2[NTOK * EMB];
__device__ __half g_ff[NTOK * FFD];
__device__ __half g_WqkvT[3 * EMB * EMB];
__device__ float  g_bqkv[3 * EMB];
__device__ __half g_WoT[EMB * EMB];
__device__ __half g_W1T[EMB * FFD];
__device__ __half g_W2T[FFD * EMB];

// ---------------- small helpers --------------------------------------------
__device__ __forceinline__ uint32_t smem_u32(const void* p) {
    uint32_t a;
    asm("{ .reg .u64 t; cvta.to.shared.u64 t, %1; cvt.u32.u64 %0, t; }"
        : "=r"(a) : "l"(p));
    return a;
}
__device__ __forceinline__ void cp16(uint32_t dst, const void* src) {
    asm volatile("cp.async.cg.shared.global [%0], [%1], 16;"
                 :: "r"(dst), "l"(src) : "memory");
}

// m16n8k16 fp16 mma, f32 accumulate (family-portable, sm_80+)
#define MMA_F16(d, a, b)                                                      \
    asm volatile("mma.sync.aligned.m16n8k16.row.col.f32.f16.f16.f32 "         \
        "{%0,%1,%2,%3}, {%4,%5,%6,%7}, {%8,%9}, {%0,%1,%2,%3};"               \
        : "+f"((d)[0]), "+f"((d)[1]), "+f"((d)[2]), "+f"((d)[3])              \
        : "r"((a)[0]), "r"((a)[1]), "r"((a)[2]), "r"((a)[3]),                 \
          "r"((b)[0]), "r"((b)[1]))

// transposed 8x8 b16 ldmatrix x4 (attention only — proven pattern/pitch)
#define LDSM4T(r0, r1, r2, r3, addr)                                          \
    asm volatile("ldmatrix.sync.aligned.m8n8.x4.trans.shared.b16 "            \
        "{%0,%1,%2,%3}, [%4];"                                                \
        : "=r"(r0), "=r"(r1), "=r"(r2), "=r"(r3) : "r"(addr))

#define PITCH 72                        // halves per smem row
#define PITCH2 (PITCH * 2)              // bytes per row
#define TILE_H (128 * PITCH)            // halves per 128-row tile
#define BUF_H  (2 * TILE_H)             // A + B per stage (halves)
#define GSMEM_BYTES (3 * BUF_H * 2)     // 110592 B, 3-stage

// ---------------- fp16 tensor-core GEMM: C = A[M,K] @ Bt[N,K]^T + bias -----
// 128 threads / CTA, 4 warps, warp tile 64x64 (high ILP, latency-bound fix).
// MODE 1: GELU -> half Ch   MODE 2: + residual R -> float Cf
// MODE 3: qkv split (q-segment scaled by 0.125)
template <int MODE>
__global__ __launch_bounds__(128) void gemm_mma(
    const __half* __restrict__ A, const __half* __restrict__ Bt,
    const float* __restrict__ bias, const float* __restrict__ R,
    float* __restrict__ Cf, __half* __restrict__ Ch,
    __half* __restrict__ Ch2, __half* __restrict__ Ch3,
    int M, int N, int K)
{
    extern __shared__ __half smh[];
    uint32_t sb = smem_u32(smh);

    int tid = threadIdx.x, wid = tid >> 5, lane = tid & 31;
    int tr = lane >> 2, tc = lane & 3;
    int wm0 = (wid >> 1) * 64, wn0 = (wid & 1) * 64;
    int m0 = blockIdx.y * 128, n0 = blockIdx.x * 128;

    float acc[4][8][4];
    #pragma unroll
    for (int i = 0; i < 4; i++)
        #pragma unroll
        for (int j = 0; j < 8; j++)
            #pragma unroll
            for (int r = 0; r < 4; r++) acc[i][j][r] = 0.f;

    const int NC = K >> 6;    // K-chunks of 64

    auto load_chunk = [&](int c) {
        uint32_t ab = sb + (uint32_t)(c % 3) * (BUF_H * 2);
        uint32_t bb = ab + TILE_H * 2;
        const __half* Ap = A + (size_t)m0 * K + (c << 6);
        const __half* Bp = Bt + (size_t)n0 * K + (c << 6);
        #pragma unroll
        for (int i = 0; i < 8; i++) {
            int gid = (i << 7) + tid;          // 0..1023
            int row = gid >> 3, g = gid & 7;   // 128 rows x 8 16B-groups
            uint32_t doff = (uint32_t)row * PITCH2 + (uint32_t)g * 16;
            cp16(ab + doff, Ap + (size_t)row * K + g * 8);
            cp16(bb + doff, Bp + (size_t)row * K + g * 8);
        }
        asm volatile("cp.async.commit_group;" ::: "memory");
    };

    load_chunk(0);
    load_chunk(1);
    for (int c = 0; c < NC; c++) {
        if (c + 1 < NC)
            asm volatile("cp.async.wait_group 1;" ::: "memory");
        else
            asm volatile("cp.async.wait_group 0;" ::: "memory");
        __syncthreads();        // single barrier per chunk (3-stage)
        if (c + 2 < NC) load_chunk(c + 2);

        const __half* Af = smh + (size_t)(c % 3) * BUF_H;
        const __half* Bf = Af + TILE_H;
        #pragma unroll
        for (int kk = 0; kk < 4; kk++) {      // 4 x k16
            int k0 = kk << 4;
            uint32_t a[4][4];
            #pragma unroll
            for (int mf = 0; mf < 4; mf++) {
                int r = wm0 + mf * 16 + tr;
                a[mf][0] = *(const uint32_t*)&Af[r * PITCH + k0 + 2 * tc];
                a[mf][1] = *(const uint32_t*)&Af[(r + 8) * PITCH + k0 + 2 * tc];
                a[mf][2] = *(const uint32_t*)&Af[r * PITCH + k0 + 8 + 2 * tc];
                a[mf][3] = *(const uint32_t*)&Af[(r + 8) * PITCH + k0 + 8 + 2 * tc];
            }
            uint32_t b[8][2];
            #pragma unroll
            for (int nf = 0; nf < 8; nf++) {
                int r = wn0 + nf * 8 + tr;
                b[nf][0] = *(const uint32_t*)&Bf[r * PITCH + k0 + 2 * tc];
                b[nf][1] = *(const uint32_t*)&Bf[r * PITCH + k0 + 8 + 2 * tc];
            }
            #pragma unroll
            for (int mf = 0; mf < 4; mf++)
                #pragma unroll
                for (int nf = 0; nf < 8; nf++)
                    MMA_F16(acc[mf][nf], a[mf], b[nf]);
        }
    }

    // epilogue
    #pragma unroll
    for (int mf = 0; mf < 4; mf++) {
        int rbase = m0 + wm0 + mf * 16 + tr;
        #pragma unroll
        for (int nf = 0; nf < 8; nf++) {
            int col = wn0 + nf * 8 + tc * 2;
            float b0 = bias[n0 + col], b1 = bias[n0 + col + 1];
            float v0 = acc[mf][nf][0] + b0;
            float v1 = acc[mf][nf][1] + b1;
            float v2 = acc[mf][nf][2] + b0;
            float v3 = acc[mf][nf][3] + b1;
            if (MODE == 1) {
                #define GELU(v) (0.5f * (v) * (1.0f + tanhf(0.7978845608028654f * ((v) + 0.044715f * (v) * (v) * (v)))))
                v0 = GELU(v0); v1 = GELU(v1); v2 = GELU(v2); v3 = GELU(v3);
                #undef GELU
                *(__half2*)(Ch + (size_t)rbase * N + n0 + col) = __floats2half2_rn(v0, v1);
                *(__half2*)(Ch + (size_t)(rbase + 8) * N + n0 + col) = __floats2half2_rn(v2, v3);
            } else if (MODE == 2) {
                float2 r0 = *(const float2*)(R + (size_t)rbase * N + n0 + col);
                float2 r1 = *(const float2*)(R + (size_t)(rbase + 8) * N + n0 + col);
                v0 += r0.x; v1 += r0.y; v2 += r1.x; v3 += r1.y;
                *(float2*)(Cf + (size_t)rbase * N + n0 + col) = make_float2(v0, v1);
                *(float2*)(Cf + (size_t)(rbase + 8) * N + n0 + col) = make_float2(v2, v3);
            } else {
                int seg = n0 >> 10;
                __half* Out = (seg == 0) ? Ch : (seg == 1) ? Ch2 : Ch3;
                if (seg == 0) {  // q: fold in 1/sqrt(64)
                    v0 *= 0.125f; v1 *= 0.125f; v2 *= 0.125f; v3 *= 0.125f;
                }
                int oc = (n0 & 1023) + col;
                *(__half2*)(Out + (size_t)rbase * EMB + oc) = __floats2half2_rn(v0, v1);
                *(__half2*)(Out + (size_t)(rbase + 8) * EMB + oc) = __floats2half2_rn(v2, v3);
            }
        }
    }
}

// ---------------- weight prep (R13-proven transpose path) -------------------
__global__ __launch_bounds__(256) void prep_qkv(
    const float* __restrict__ Wq, const float* __restrict__ Wk,
    const float* __restrict__ Wv,
    const float* __restrict__ bq, const float* __restrict__ bk,
    const float* __restrict__ bv,
    __half* __restrict__ WqkvT, float* __restrict__ bqkv)
{
    __shared__ float t[32][33];
    int z = blockIdx.z;
    const float* W = (z == 0) ? Wq : (z == 1) ? Wk : Wv;
    const float* bs = (z == 0) ? bq : (z == 1) ? bk : bv;
    __half* Wt = WqkvT + (size_t)z * EMB * EMB;
    int bx = blockIdx.x * 32, by = blockIdx.y * 32;
    int x = threadIdx.x, y = threadIdx.y;
    if (blockIdx.y == 0 && y == 0)
        bqkv[z * EMB + bx + x] = bs[bx + x];
    #pragma unroll
    for (int r = 0; r < 32; r += 8)
        t[y + r][x] = W[(size_t)(by + y + r) * EMB + bx + x];
    __syncthreads();
    #pragma unroll
    for (int r = 0; r < 32; r += 8)
        Wt[(size_t)(bx + y + r) * EMB + by + x] = __float2half_rn(t[x][y + r]);
}

__global__ __launch_bounds__(256) void prep_t3(
    const float* __restrict__ Wo, const float* __restrict__ W1,
    const float* __restrict__ W2,
    __half* __restrict__ WoT, __half* __restrict__ W1T, __half* __restrict__ W2T)
{
    __shared__ float t[32][33];
    int bid = blockIdx.x;
    const float* W; __half* Wt; int K, N, tix, tiy;
    if (bid < 1024) {
        W = Wo; Wt = WoT; K = EMB; N = EMB;
        tix = bid & 31; tiy = bid >> 5;
    } else if (bid < 5120) {
        int b = bid - 1024;
        W = W1; Wt = W1T; K = EMB; N = FFD;
        tix = b & 127; tiy = b >> 7;
    } else {
        int b = bid - 5120;
        W = W2; Wt = W2T; K = FFD; N = EMB;
        tix = b & 31; tiy = b >> 5;
    }
    int bx = tix * 32, by = tiy * 32;
    int x = threadIdx.x, y = threadIdx.y;
    #pragma unroll
    for (int r = 0; r < 32; r += 8)
        t[y + r][x] = W[(size_t)(by + y + r) * N + bx + x];
    __syncthreads();
    #pragma unroll
    for (int r = 0; r < 32; r += 8)
        Wt[(size_t)(bx + y + r) * K + by + x] = __float2half_rn(t[x][y + r]);
}

// ---------------- layernorm: fp32 in, fp16 out ------------------------------
__global__ __launch_bounds__(256) void ln_kernel(
    const float* __restrict__ x, const float* __restrict__ g,
    const float* __restrict__ b, __half* __restrict__ out)
{
    int row = blockIdx.x;
    const float4* xr = (const float4*)(x + (size_t)row * EMB);
    float4 v = xr[threadIdx.x];
    float s  = v.x + v.y + v.z + v.w;
    float ss = v.x * v.x + v.y * v.y + v.z * v.z + v.w * v.w;
    #pragma unroll
    for (int o = 16; o; o >>= 1) {
        s  += __shfl_xor_sync(0xFFFFFFFFu, s,  o);
        ss += __shfl_xor_sync(0xFFFFFFFFu, ss, o);
    }
    __shared__ float sbuf[8], ssbuf[8];
    int w = threadIdx.x >> 5, l = threadIdx.x & 31;
    if (l == 0) { sbuf[w] = s; ssbuf[w] = ss; }
    __syncthreads();
    if (w == 0) {
        float s2  = (l < 8) ? sbuf[l]  : 0.f;
        float ss2 = (l < 8) ? ssbuf[l] : 0.f;
        #pragma unroll
        for (int o = 4; o; o >>= 1) {
            s2  += __shfl_xor_sync(0xFFFFFFFFu, s2,  o);
            ss2 += __shfl_xor_sync(0xFFFFFFFFu, ss2, o);
        }
        if (l == 0) { sbuf[0] = s2 * (1.f / EMB); ssbuf[0] = ss2 * (1.f / EMB); }
    }
    __syncthreads();
    float mean = sbuf[0];
    float var  = ssbuf[0] - mean * mean;
    float r    = rsqrtf(var + 1e-5f);
    float4 gg = ((const float4*)g)[threadIdx.x];
    float4 bb = ((const float4*)b)[threadIdx.x];
    __half2 h01 = __floats2half2_rn((v.x - mean) * r * gg.x + bb.x,
                                    (v.y - mean) * r * gg.y + bb.y);
    __half2 h23 = __floats2half2_rn((v.z - mean) * r * gg.z + bb.z,
                                    (v.w - mean) * r * gg.w + bb.w);
    uint2 u;
    u.x = *(uint32_t*)&h01; u.y = *(uint32_t*)&h23;
    ((uint2*)(out + (size_t)row * EMB))[threadIdx.x] = u;
}

// ---------------- flash attention, fp16 MMA, register-resident P ------------
// Unchanged from passing R12/R13.
#define KB_H   (64 * PITCH)
#define STG_H  (2 * KB_H)
#define ATTN_SMEM ((2 * STG_H + 128 * PITCH) * 2)   // 55296 B
__global__ __launch_bounds__(256) void attn_mma(
    const __half* __restrict__ Q, const __half* __restrict__ K,
    const __half* __restrict__ V, __half* __restrict__ O)
{
    extern __shared__ __half smh[];
    __half* QP = smh + 2 * STG_H;
    uint32_t smb = smem_u32(smh);

    int qt = blockIdx.x, h = blockIdx.y, b = blockIdx.z;
    int tid = threadIdx.x, wid = tid >> 5, lane = tid & 31;
    int tr = lane >> 2, tc = lane & 3;

    size_t qrow0 = (size_t)b * SEQ + qt * 128;

    for (int i = tid; i < 128 * 8; i += 256) {
        int r = i >> 3, g = i & 7;
        uint4 u = *(const uint4*)(Q + (qrow0 + r) * EMB + h * 64 + g * 8);
        *(uint4*)&QP[r * PITCH + g * 8] = u;
    }
    __syncthreads();

    int qr = wid * 16;
    uint32_t qf[4][4];
    #pragma unroll
    for (int kk = 0; kk < 4; kk++) {
        int k0 = kk << 4;
        qf[kk][0] = *(const uint32_t*)&QP[(qr + tr) * PITCH + k0 + 2 * tc];
        qf[kk][1] = *(const uint32_t*)&QP[(qr + tr + 8) * PITCH + k0 + 2 * tc];
        qf[kk][2] = *(const uint32_t*)&QP[(qr + tr) * PITCH + k0 + 8 + 2 * tc];
        qf[kk][3] = *(const uint32_t*)&QP[(qr + tr + 8) * PITCH + k0 + 8 + 2 * tc];
    }

    int lm_krow = (lane & 7) + ((lane >> 3) & 1) * 8;
    int lm_ncol = (lane >> 4) * 8;

    float oacc[8][4];
    #pragma unroll
    for (int nf = 0; nf < 8; nf++)
        #pragma unroll
        for (int r = 0; r < 4; r++) oacc[nf][r] = 0.f;
    float m0 = -1e30f, m1 = -1e30f, l0 = 0.f, l1 = 0.f;

    size_t krow0 = (size_t)b * SEQ;
    auto load_tile = [&](int kt) {
        uint32_t stg = smb + (uint32_t)(kt & 1) * (STG_H * 2);
        for (int i = tid; i < 1024; i += 256) {
            int tile = i >> 9, idx = i & 511;
            int r = idx >> 3, g = idx & 7;
            size_t src = (krow0 + kt * 64 + r) * EMB + h * 64 + g * 8;
            uint32_t doff = (uint32_t)tile * (KB_H * 2) + (uint32_t)r * PITCH2 + g * 16;
            cp16(stg + doff, ((tile == 0) ? K : V) + src);
        }
        asm volatile("cp.async.commit_group;" ::: "memory");
    };

    load_tile(0);
    for (int kt = 0; kt < SEQ / 64; kt++) {
        asm volatile("cp.async.wait_group 0;" ::: "memory");
        __syncthreads();
        if (kt + 1 < SEQ / 64) load_tile(kt + 1);

        const __half* Ks = smh + (size_t)(kt & 1) * STG_H;
        uint32_t vbase = smb + (uint32_t)(kt & 1) * (STG_H * 2) + KB_H * 2;

        float sacc[8][4];
        #pragma unroll
        for (int nf = 0; nf < 8; nf++)
            #pragma unroll
            for (int r = 0; r < 4; r++) sacc[nf][r] = 0.f;
        #pragma unroll
        for (int kk = 0; kk < 4; kk++) {
            int k0 = kk << 4;
            #pragma unroll
            for (int nf = 0; nf < 8; nf++) {
                uint32_t bfr[2];
                bfr[0] = *(const uint32_t*)&Ks[(nf * 8 + tr) * PITCH + k0 + 2 * tc];
                bfr[1] = *(const uint32_t*)&Ks[(nf * 8 + tr) * PITCH + k0 + 8 + 2 * tc];
                MMA_F16(sacc[nf], qf[kk], bfr);
            }
        }

        float mt0 = -1e30f, mt1 = -1e30f;
        #pragma unroll
        for (int nf = 0; nf < 8; nf++) {
            mt0 = fmaxf(mt0, fmaxf(sacc[nf][0], sacc[nf][1]));
            mt1 = fmaxf(mt1, fmaxf(sacc[nf][2], sacc[nf][3]));
        }
        mt0 = fmaxf(mt0, __shfl_xor_sync(0xFFFFFFFFu, mt0, 1));
        mt0 = fmaxf(mt0, __shfl_xor_sync(0xFFFFFFFFu, mt0, 2));
        mt1 = fmaxf(mt1, __shfl_xor_sync(0xFFFFFFFFu, mt1, 1));
        mt1 = fmaxf(mt1, __shfl_xor_sync(0xFFFFFFFFu, mt1, 2));
        float mn0 = fmaxf(m0, mt0), mn1 = fmaxf(m1, mt1);
        float a0 = __expf(m0 - mn0), a1 = __expf(m1 - mn1);
        float rs0 = 0.f, rs1 = 0.f;
        uint32_t ph01[8], ph23[8];
        #pragma unroll
        for (int nf = 0; nf < 8; nf++) {
            float p0 = __expf(sacc[nf][0] - mn0);
            float p1 = __expf(sacc[nf][1] - mn0);
            float p2 = __expf(sacc[nf][2] - mn1);
            float p3 = __expf(sacc[nf][3] - mn1);
            rs0 += p0 + p1; rs1 += p2 + p3;
            __half2 h01 = __floats2half2_rn(p0, p1);
            __half2 h23 = __floats2half2_rn(p2, p3);
            ph01[nf] = *(uint32_t*)&h01;
            ph23[nf] = *(uint32_t*)&h23;
        }
        rs0 += __shfl_xor_sync(0xFFFFFFFFu, rs0, 1);
        rs0 += __shfl_xor_sync(0xFFFFFFFFu, rs0, 2);
        rs1 += __shfl_xor_sync(0xFFFFFFFFu, rs1, 1);
        rs1 += __shfl_xor_sync(0xFFFFFFFFu, rs1, 2);
        l0 = l0 * a0 + rs0; l1 = l1 * a1 + rs1;
        m0 = mn0; m1 = mn1;
        #pragma unroll
        for (int nf = 0; nf < 8; nf++) {
            oacc[nf][0] *= a0; oacc[nf][1] *= a0;
            oacc[nf][2] *= a1; oacc[nf][3] *= a1;
        }

        #pragma unroll
        for (int kk = 0; kk < 4; kk++) {
            uint32_t pa[4] = {ph01[2 * kk], ph23[2 * kk],
                              ph01[2 * kk + 1], ph23[2 * kk + 1]};
            #pragma unroll
            for (int nfp = 0; nfp < 4; nfp++) {
                uint32_t v0, v1, v2, v3;
                uint32_t maddr = vbase +
                    (uint32_t)(kk * 16 + lm_krow) * PITCH2 +
                    (uint32_t)(nfp * 16 + lm_ncol) * 2;
                LDSM4T(v0, v1, v2, v3, maddr);
                uint32_t bA[2] = {v0, v1}, bB[2] = {v2, v3};
                MMA_F16(oacc[2 * nfp],     pa, bA);
                MMA_F16(oacc[2 * nfp + 1], pa, bB);
            }
        }
    }

    float i0 = 1.f / l0, i1 = 1.f / l1;
    size_t r0 = (qrow0 + qr + tr) * EMB + h * 64;
    size_t r1 = (qrow0 + qr + tr + 8) * EMB + h * 64;
    #pragma unroll
    for (int nf = 0; nf < 8; nf++) {
        int col = nf * 8 + tc * 2;
        *(__half2*)(O + r0 + col) = __floats2half2_rn(oacc[nf][0] * i0, oacc[nf][1] * i0);
        *(__half2*)(O + r1 + col) = __floats2half2_rn(oacc[nf][2] * i1, oacc[nf][3] * i1);
    }
}

// ---------------- launch ----------------------------------------------------
extern "C" void kernel_launch(void* const* d_in, const int* in_sizes, int n_in,
                              void* d_out, int out_size)
{
    const float* x     = (const float*)d_in[0];
    const float* Wq    = (const float*)d_in[1];
    const float* bq    = (const float*)d_in[2];
    const float* Wk    = (const float*)d_in[3];
    const float* bk    = (const float*)d_in[4];
    const float* Wv    = (const float*)d_in[5];
    const float* bv    = (const float*)d_in[6];
    const float* Wo    = (const float*)d_in[7];
    const float* bo    = (const float*)d_in[8];
    const float* W1    = (const float*)d_in[9];
    const float* b1    = (const float*)d_in[10];
    const float* W2    = (const float*)d_in[11];
    const float* b2    = (const float*)d_in[12];
    const float* ln1_g = (const float*)d_in[13];
    const float* ln1_b = (const float*)d_in[14];
    const float* ln2_g = (const float*)d_in[15];
    const float* ln2_b = (const float*)d_in[16];

    __half *ln1, *q, *k, *v, *attn, *ln2, *ff;
    __half *WqkvT, *WoT, *W1T, *W2T;
    float *x1, *bqkv;
    cudaGetSymbolAddress((void**)&ln1,   g_ln1);
    cudaGetSymbolAddress((void**)&q,     g_q);
    cudaGetSymbolAddress((void**)&k,     g_k);
    cudaGetSymbolAddress((void**)&v,     g_v);
    cudaGetSymbolAddress((void**)&attn,  g_attn);
    cudaGetSymbolAddress((void**)&x1,    g_x1);
    cudaGetSymbolAddress((void**)&ln2,   g_ln2);
    cudaGetSymbolAddress((void**)&ff,    g_ff);
    cudaGetSymbolAddress((void**)&WqkvT, g_WqkvT);
    cudaGetSymbolAddress((void**)&bqkv,  g_bqkv);
    cudaGetSymbolAddress((void**)&WoT,   g_WoT);
    cudaGetSymbolAddress((void**)&W1T,   g_W1T);
    cudaGetSymbolAddress((void**)&W2T,   g_W2T);

    cudaFuncSetAttribute(gemm_mma<1>, cudaFuncAttributeMaxDynamicSharedMemorySize, GSMEM_BYTES);
    cudaFuncSetAttribute(gemm_mma<2>, cudaFuncAttributeMaxDynamicSharedMemorySize, GSMEM_BYTES);
    cudaFuncSetAttribute(gemm_mma<3>, cudaFuncAttributeMaxDynamicSharedMemorySize, GSMEM_BYTES);
    cudaFuncSetAttribute(attn_mma, cudaFuncAttributeMaxDynamicSharedMemorySize, ATTN_SMEM);

    dim3 tb(32, 8);
    // launch 0
    prep_qkv<<<dim3(32, 32, 3), tb>>>(Wq, Wk, Wv, bq, bk, bv, WqkvT, bqkv);
    // launch 1
    prep_t3<<<9216, tb>>>(Wo, W1, W2, WoT, W1T, W2T);
    // launch 2
    ln_kernel<<<NTOK, 256>>>(x, ln1_g, ln1_b, ln1);
    // launch 3 (ncu capture slot): fused QKV GEMM
    gemm_mma<3><<<dim3(3 * EMB / 128, NTOK / 128), 128, GSMEM_BYTES>>>(
        ln1, WqkvT, bqkv, nullptr, nullptr, q, k, v, NTOK, 3 * EMB, EMB);
    // launch 4
    attn_mma<<<dim3(SEQ / 128, 16, 2), 256, ATTN_SMEM>>>(q, k, v, attn);
    // launch 5
    gemm_mma<2><<<dim3(EMB / 128, NTOK / 128), 128, GSMEM_BYTES>>>(
        attn, WoT, bo, x, x1, nullptr, nullptr, nullptr, NTOK, EMB, EMB);
    // launch 6
    ln_kernel<<<NTOK, 256>>>(x1, ln2_g, ln2_b, ln2);
    // launch 7
    gemm_mma<1><<<dim3(FFD / 128, NTOK / 128), 128, GSMEM_BYTES>>>(
        ln2, W1T, b1, nullptr, nullptr, ff, nullptr, nullptr, NTOK, FFD, EMB);
    // launch 8
    gemm_mma<2><<<dim3(EMB / 128, NTOK / 128), 128, GSMEM_BYTES>>>(
        ff, W2T, b2, x1, (float*)d_out, nullptr, nullptr, nullptr, NTOK, EMB, FFD);
}